// round 1
// baseline (speedup 1.0000x reference)
#include <cuda_runtime.h>
#include <cuda_bf16.h>
#include <cstdint>

#define B_  32
#define C_  768
#define HW_ 1024

// Scratch (device globals — allocation-free per harness rules)
__device__ __nv_bfloat16 g_Xn[B_ * C_ * HW_];   // normalized input, bf16
__device__ float         g_A[B_ * C_];          // per (b,c) gate

// ---------------------------------------------------------------------------
// Kernel 1: channel RMSNorm, fp32 -> bf16
// grid (HW/256, B), 256 threads. Each thread owns one (b,hw).
// ---------------------------------------------------------------------------
__global__ void norm_kernel(const float* __restrict__ X) {
    int b  = blockIdx.y;
    int hw = blockIdx.x * 256 + threadIdx.x;
    const float* xp = X + (size_t)b * C_ * HW_ + hw;

    float s0 = 0.f, s1 = 0.f, s2 = 0.f, s3 = 0.f;
#pragma unroll 8
    for (int c = 0; c < C_; c += 4) {
        float x0 = xp[(c + 0) * HW_];
        float x1 = xp[(c + 1) * HW_];
        float x2 = xp[(c + 2) * HW_];
        float x3 = xp[(c + 3) * HW_];
        s0 = fmaf(x0, x0, s0);
        s1 = fmaf(x1, x1, s1);
        s2 = fmaf(x2, x2, s2);
        s3 = fmaf(x3, x3, s3);
    }
    float inv = rsqrtf((s0 + s1 + s2 + s3) * (1.0f / C_) + 1e-6f);

    __nv_bfloat16* op = g_Xn + (size_t)b * C_ * HW_ + hw;
#pragma unroll 4
    for (int c = 0; c < C_; c++)
        op[c * HW_] = __float2bfloat16(xp[c * HW_] * inv);
}

// ---------------------------------------------------------------------------
// Kernel 2: fused KV-GEMM + cosine-sim reduction.
// Block = (channel tile of 64, batch). 256 threads = 8 warps (4 M x 2 N).
// GEMM tile: M=128 rows (interleaved Wk/Wv per 16-row group), N=64, K=32/stage.
// Weight panel persistent in SMEM; Xn double-buffered.
// ---------------------------------------------------------------------------
#define MT 128
#define NT 64
#define KT 32
#define A_STRIDE 776   // 768 + 8 pad -> conflict-free ldmatrix
#define B_STRIDE 72    // 64 + 8 pad

#define SMEM_A_BYTES (MT * A_STRIDE * 2)
#define SMEM_B_BYTES (2 * KT * B_STRIDE * 2)
#define SMEM_S_BYTES (64 * 3 * 4)
#define SMEM_TOTAL   (SMEM_A_BYTES + SMEM_B_BYTES + SMEM_S_BYTES)

__global__ void __launch_bounds__(256, 1)
attn_gemm_kernel(const float* __restrict__ Win) {
    extern __shared__ char smem[];
    __nv_bfloat16* sA = (__nv_bfloat16*)smem;                     // [128][776]
    __nv_bfloat16* sB = (__nv_bfloat16*)(smem + SMEM_A_BYTES);    // [2][32][72]
    float*         sS = (float*)(smem + SMEM_A_BYTES + SMEM_B_BYTES); // [64][3]

    const int tid   = threadIdx.x;
    const int b     = blockIdx.y;
    const int cbase = blockIdx.x * 64;

    if (tid < 192) sS[tid] = 0.f;

    // Load weight panel with Wk/Wv interleave:
    // SMEM row a: g=a/16, r=a%16; channel = cbase + g*8 + (r%8); r<8 -> Wk, r>=8 -> Wv
    for (int idx = tid; idx < MT * C_; idx += 256) {
        int a   = idx / C_;
        int col = idx - a * C_;
        int g = a >> 4, r = a & 15;
        int wrow = (r < 8) ? (cbase + g * 8 + r)
                           : (C_ + cbase + g * 8 + (r - 8));
        sA[a * A_STRIDE + col] = __float2bfloat16(Win[(size_t)wrow * C_ + col]);
    }
    __syncthreads();

    const __nv_bfloat16* Xn = g_Xn + (size_t)b * C_ * HW_;

    const int warp = tid >> 5, lane = tid & 31;
    const int wm = warp >> 1, wn = warp & 1;

    // Xn stage loader: thread -> (row 0..31, 16B segment 0..7)
    const int brow = tid >> 3;
    const int bseg = (tid & 7) * 8;

    float skv[2] = {0.f, 0.f}, skk[2] = {0.f, 0.f}, svv[2] = {0.f, 0.f};

    const uint32_t sA_base = (uint32_t)__cvta_generic_to_shared(sA);
    const uint32_t sB_base = (uint32_t)__cvta_generic_to_shared(sB);

    for (int n0 = 0; n0 < HW_; n0 += NT) {
        float acc[2][4][4];
#pragma unroll
        for (int mi = 0; mi < 2; mi++)
#pragma unroll
            for (int ni = 0; ni < 4; ni++)
#pragma unroll
                for (int q = 0; q < 4; q++) acc[mi][ni][q] = 0.f;

        uint4 pre = *(const uint4*)(Xn + (size_t)brow * HW_ + n0 + bseg);

#pragma unroll 1
        for (int ks = 0; ks < C_ / KT; ks++) {
            const int buf = ks & 1;
            // publish current stage
            *(uint4*)(sB + buf * KT * B_STRIDE + brow * B_STRIDE + bseg) = pre;
            __syncthreads();
            // prefetch next stage
            if (ks + 1 < C_ / KT)
                pre = *(const uint4*)(Xn + (size_t)((ks + 1) * KT + brow) * HW_ + n0 + bseg);

#pragma unroll
            for (int kk = 0; kk < KT; kk += 16) {
                const int kabs = ks * KT + kk;
                uint32_t a_frag[2][4];
#pragma unroll
                for (int mi = 0; mi < 2; mi++) {
                    int row = wm * 32 + mi * 16 + (lane & 15);
                    uint32_t addr = sA_base +
                        (uint32_t)(row * A_STRIDE + kabs + ((lane >> 4) << 3)) * 2u;
                    asm volatile(
                        "ldmatrix.sync.aligned.m8n8.x4.shared.b16 {%0,%1,%2,%3}, [%4];"
                        : "=r"(a_frag[mi][0]), "=r"(a_frag[mi][1]),
                          "=r"(a_frag[mi][2]), "=r"(a_frag[mi][3])
                        : "r"(addr));
                }
                uint32_t b_frag[4][2];
#pragma unroll
                for (int nj = 0; nj < 2; nj++) {
                    int krow = kk + (lane & 15);
                    int ncol = wn * 32 + nj * 16 + ((lane >> 4) << 3);
                    uint32_t addr = sB_base +
                        (uint32_t)(buf * KT * B_STRIDE + krow * B_STRIDE + ncol) * 2u;
                    uint32_t r0, r1, r2, r3;
                    asm volatile(
                        "ldmatrix.sync.aligned.m8n8.x4.trans.shared.b16 {%0,%1,%2,%3}, [%4];"
                        : "=r"(r0), "=r"(r1), "=r"(r2), "=r"(r3)
                        : "r"(addr));
                    b_frag[nj * 2 + 0][0] = r0; b_frag[nj * 2 + 0][1] = r1;
                    b_frag[nj * 2 + 1][0] = r2; b_frag[nj * 2 + 1][1] = r3;
                }
#pragma unroll
                for (int mi = 0; mi < 2; mi++)
#pragma unroll
                    for (int ni = 0; ni < 4; ni++) {
                        asm volatile(
                            "mma.sync.aligned.m16n8k16.row.col.f32.bf16.bf16.f32 "
                            "{%0,%1,%2,%3}, {%4,%5,%6,%7}, {%8,%9}, {%0,%1,%2,%3};"
                            : "+f"(acc[mi][ni][0]), "+f"(acc[mi][ni][1]),
                              "+f"(acc[mi][ni][2]), "+f"(acc[mi][ni][3])
                            : "r"(a_frag[mi][0]), "r"(a_frag[mi][1]),
                              "r"(a_frag[mi][2]), "r"(a_frag[mi][3]),
                              "r"(b_frag[ni][0]), "r"(b_frag[ni][1]));
                    }
            }
        }

        // Per-chunk epilogue: c0,c1 = K row, c2,c3 = V row of SAME channel,
        // same columns -> reduce entirely in registers.
#pragma unroll
        for (int mi = 0; mi < 2; mi++)
#pragma unroll
            for (int ni = 0; ni < 4; ni++) {
                float k0 = acc[mi][ni][0], k1 = acc[mi][ni][1];
                float v0 = acc[mi][ni][2], v1 = acc[mi][ni][3];
                skv[mi] += k0 * v0 + k1 * v1;
                skk[mi] += k0 * k0 + k1 * k1;
                svv[mi] += v0 * v0 + v1 * v1;
            }
        __syncthreads();  // all reads of sB done before next chunk republishes
    }

    // Quad reduce (lanes 4q..4q+3 share a channel)
#pragma unroll
    for (int mi = 0; mi < 2; mi++) {
        skv[mi] += __shfl_down_sync(0xffffffffu, skv[mi], 1);
        skv[mi] += __shfl_down_sync(0xffffffffu, skv[mi], 2);
        skk[mi] += __shfl_down_sync(0xffffffffu, skk[mi], 1);
        skk[mi] += __shfl_down_sync(0xffffffffu, skk[mi], 2);
        svv[mi] += __shfl_down_sync(0xffffffffu, svv[mi], 1);
        svv[mi] += __shfl_down_sync(0xffffffffu, svv[mi], 2);
    }
    if ((lane & 3) == 0) {
#pragma unroll
        for (int mi = 0; mi < 2; mi++) {
            int chl = (wm * 2 + mi) * 8 + (lane >> 2);
            atomicAdd(&sS[chl * 3 + 0], skv[mi]);
            atomicAdd(&sS[chl * 3 + 1], skk[mi]);
            atomicAdd(&sS[chl * 3 + 2], svv[mi]);
        }
    }
    __syncthreads();

    if (tid < 64) {
        float kv = sS[tid * 3 + 0];
        float kk2 = sS[tid * 3 + 1];
        float vv2 = sS[tid * 3 + 2];
        float cosv = kv / ((sqrtf(kk2) + 1e-12f) * (sqrtf(vv2) + 1e-12f));
        g_A[b * C_ + cbase + tid] = 0.5f * cosv + 0.5f;
    }
}

// ---------------------------------------------------------------------------
// Kernel 3: out = A[b,c] * X   (float4 vectorized)
// ---------------------------------------------------------------------------
__global__ void scale_kernel(const float* __restrict__ X, float* __restrict__ out) {
    int i = blockIdx.x * blockDim.x + threadIdx.x;
    const int n4 = B_ * C_ * HW_ / 4;
    if (i < n4) {
        float4 x = ((const float4*)X)[i];
        float a = g_A[i >> 8];   // (i*4)/1024 = b*768 + c
        float4 o;
        o.x = a * x.x; o.y = a * x.y; o.z = a * x.z; o.w = a * x.w;
        ((float4*)out)[i] = o;
    }
}

// ---------------------------------------------------------------------------
extern "C" void kernel_launch(void* const* d_in, const int* in_sizes, int n_in,
                              void* d_out, int out_size) {
    const float* X = (const float*)d_in[0];
    const float* W = (const float*)d_in[1];
    float* out = (float*)d_out;

    cudaFuncSetAttribute(attn_gemm_kernel,
                         cudaFuncAttributeMaxDynamicSharedMemorySize, SMEM_TOTAL);

    norm_kernel<<<dim3(HW_ / 256, B_), 256>>>(X);
    attn_gemm_kernel<<<dim3(C_ / 64, B_), 256, SMEM_TOTAL>>>(W);

    const int n4 = B_ * C_ * HW_ / 4;
    scale_kernel<<<(n4 + 255) / 256, 256>>>(X, out);
}

// round 3
// speedup vs baseline: 2.5895x; 2.5895x over previous
#include <cuda_runtime.h>
#include <cuda_bf16.h>
#include <cstdint>

#define B_   32
#define C_   768
#define HW_  1024

// -------- device scratch (allocation-free) --------
__device__ __nv_bfloat16 g_Xn[B_ * C_ * HW_];     // normalized X, bf16
__device__ __nv_bfloat16 g_Wb[2 * C_ * C_];       // interleaved bf16 weights [cb][128][768]
__device__ float         g_A[B_ * C_];            // per (b,c) gate

// -------- GEMM tiling --------
#define NSTG   12          // K stages of 64 per n-chunk
#define NCHUNK 16          // hw chunks of 64 columns
#define NGS    (NSTG * NCHUNK)

#define SMEM_A_BYTES (128 * 768 * 2)               // 196608, swizzled, no pad
#define SMEM_B_OFF   SMEM_A_BYTES
#define SLOT_BYTES   (64 * 64 * 2)                 // 8192 per stage
#define SMEM_S_OFF   (SMEM_B_OFF + 3 * SLOT_BYTES) // 221184
#define SMEM_TOTAL   (SMEM_S_OFF + 64 * 3 * 4)     // 221952 < 227KB

// -------- PTX helpers --------
__device__ __forceinline__ void cp16(uint32_t dst, const void* src) {
    asm volatile("cp.async.cg.shared.global [%0], [%1], 16;\n" :: "r"(dst), "l"(src) : "memory");
}
#define CP_COMMIT() asm volatile("cp.async.commit_group;\n" ::: "memory")
#define CP_WAIT(n)  asm volatile("cp.async.wait_group %0;\n" :: "n"(n) : "memory")

// ---------------------------------------------------------------------------
// Kernel 0: weight prep — fp32 -> bf16, K/V rows pre-interleaved.
// g_Wb row (cb*128 + a): g=a/16, r=a%16; r<8 -> Wk[cb*64+g*8+r], else Wv.
// ---------------------------------------------------------------------------
__global__ void wprep_kernel(const float* __restrict__ Win) {
    int i4 = blockIdx.x * 256 + threadIdx.x;
    if (i4 >= 2 * C_ * C_ / 4) return;
    int row = i4 / 192;
    int kc  = (i4 - row * 192) * 4;
    int cb = row >> 7, a = row & 127;
    int g = a >> 4, r = a & 15;
    int wrow = (r < 8) ? (cb * 64 + g * 8 + r)
                       : (C_ + cb * 64 + g * 8 + (r - 8));
    float4 v = *(const float4*)(Win + (size_t)wrow * C_ + kc);
    __nv_bfloat162 p0 = __floats2bfloat162_rn(v.x, v.y);
    __nv_bfloat162 p1 = __floats2bfloat162_rn(v.z, v.w);
    uint2 o;
    o.x = *(uint32_t*)&p0;
    o.y = *(uint32_t*)&p1;
    *(uint2*)(g_Wb + (size_t)row * C_ + kc) = o;
}

// ---------------------------------------------------------------------------
// Kernel 1: channel RMSNorm, fp32 -> bf16.  grid (16, 32) x 256 threads.
// 4 threads per hw position, each covering 192 channels.
// ---------------------------------------------------------------------------
__global__ void norm_kernel(const float* __restrict__ X) {
    __shared__ float red[256];
    int b = blockIdx.y;
    int t = threadIdx.x;
    int hw = blockIdx.x * 64 + (t & 63);
    int q  = t >> 6;
    const float* xp = X + ((size_t)b * C_ + q * 192) * HW_ + hw;

    float s = 0.f;
#pragma unroll 8
    for (int c = 0; c < 192; c++) {
        float v = xp[c * HW_];
        s = fmaf(v, v, s);
    }
    red[t] = s;
    __syncthreads();
    float tot = red[t & 63] + red[64 + (t & 63)] + red[128 + (t & 63)] + red[192 + (t & 63)];
    float inv = rsqrtf(tot * (1.0f / C_) + 1e-6f);

    __nv_bfloat16* op = g_Xn + ((size_t)b * C_ + q * 192) * HW_ + hw;
#pragma unroll 8
    for (int c = 0; c < 192; c++)
        op[c * HW_] = __float2bfloat16(xp[c * HW_] * inv);
}

// ---------------------------------------------------------------------------
// Kernel 2: fused KV-GEMM (legacy mma.sync) + cosine-sim reduction.
// grid (12, 32), 256 threads = 8 warps (4 M-warps x 2 N-warps).
// A: 128x768 bf16 panel, persistent in swizzled SMEM.
// B: 64K x 64N stages, 3-slot cp.async ring, ONE barrier per stage.
// ---------------------------------------------------------------------------
__global__ void __launch_bounds__(256, 1)
attn_gemm_kernel() {
    extern __shared__ char smem[];
    const uint32_t sb = (uint32_t)__cvta_generic_to_shared(smem);
    float* sS = (float*)(smem + SMEM_S_OFF);

    const int tid = threadIdx.x;
    const int b = blockIdx.y;
    const int cb = blockIdx.x;

    if (tid < 192) sS[tid] = 0.f;

    // ---- A panel: cp.async, XOR-swizzled (16B units within 128B rows) ----
    const __nv_bfloat16* wsrc = g_Wb + (size_t)cb * 128 * C_;
    for (int unit = tid; unit < 12288; unit += 256) {
        int row = unit / 96, c16 = unit - (unit / 96) * 96;
        uint32_t dst = sb + (uint32_t)(row * 1536 + (((c16 & 7) ^ (row & 7)) << 4) + ((c16 >> 3) << 7));
        cp16(dst, wsrc + (size_t)row * C_ + c16 * 8);
    }
    CP_COMMIT();

    const __nv_bfloat16* XnB = g_Xn + (size_t)b * C_ * HW_;
    const int warp = tid >> 5, lane = tid & 31;
    const int wm = warp >> 1, wn = warp & 1;

    // B stage loader lambda-equivalent
    const int l_krow = tid >> 3;            // 0..31 (x2 iters -> 0..63)
    const int l_n16  = tid & 7;

#define LOAD_B(gs_)                                                          \
    {                                                                        \
        int ch_ = (gs_) / NSTG, st_ = (gs_) - ch_ * NSTG, buf_ = (gs_) % 3;  \
        const __nv_bfloat16* src_ = XnB + (size_t)(st_ * 64) * HW_ + ch_ * 64; \
        _Pragma("unroll")                                                    \
        for (int i_ = 0; i_ < 2; i_++) {                                     \
            int kr_ = l_krow + i_ * 32;                                      \
            cp16(sb + SMEM_B_OFF + buf_ * SLOT_BYTES + kr_ * 128 +           \
                     ((l_n16 ^ (kr_ & 7)) << 4),                             \
                 src_ + (size_t)kr_ * HW_ + l_n16 * 8);                      \
        }                                                                    \
        CP_COMMIT();                                                         \
    }

    LOAD_B(0);
    LOAD_B(1);

    float skv[2] = {0.f, 0.f}, skk[2] = {0.f, 0.f}, svv[2] = {0.f, 0.f};
    float acc[2][4][4];

#pragma unroll 1
    for (int gs = 0; gs < NGS; gs++) {
        const int st = gs % NSTG;
        const int buf = gs % 3;

        if (gs < NGS - 1) { CP_WAIT(1); } else { CP_WAIT(0); }
        __syncthreads();
        if (gs + 2 < NGS) LOAD_B(gs + 2);

        if (st == 0) {
#pragma unroll
            for (int mi = 0; mi < 2; mi++)
#pragma unroll
                for (int ni = 0; ni < 4; ni++)
#pragma unroll
                    for (int q = 0; q < 4; q++) acc[mi][ni][q] = 0.f;
        }

        const uint32_t sBb = sb + SMEM_B_OFF + buf * SLOT_BYTES;
#pragma unroll
        for (int kk = 0; kk < 4; kk++) {
            const int c16b = st * 8 + kk * 2;
            uint32_t af[2][4];
#pragma unroll
            for (int mi = 0; mi < 2; mi++) {
                int row = wm * 32 + mi * 16 + (lane & 15);
                int c16 = c16b + (lane >> 4);
                uint32_t addr = sb + (uint32_t)(row * 1536 +
                    (((c16 & 7) ^ (row & 7)) << 4) + ((c16 >> 3) << 7));
                asm volatile(
                    "ldmatrix.sync.aligned.m8n8.x4.shared.b16 {%0,%1,%2,%3}, [%4];"
                    : "=r"(af[mi][0]), "=r"(af[mi][1]), "=r"(af[mi][2]), "=r"(af[mi][3])
                    : "r"(addr));
            }
            uint32_t bfr[4][2];
#pragma unroll
            for (int nj = 0; nj < 2; nj++) {
                int krow = kk * 16 + (lane & 15);
                int n16 = wn * 4 + nj * 2 + (lane >> 4);
                uint32_t addr = sBb + (uint32_t)(krow * 128 + ((n16 ^ (krow & 7)) << 4));
                uint32_t r0, r1, r2, r3;
                asm volatile(
                    "ldmatrix.sync.aligned.m8n8.x4.trans.shared.b16 {%0,%1,%2,%3}, [%4];"
                    : "=r"(r0), "=r"(r1), "=r"(r2), "=r"(r3)
                    : "r"(addr));
                bfr[nj * 2 + 0][0] = r0; bfr[nj * 2 + 0][1] = r1;
                bfr[nj * 2 + 1][0] = r2; bfr[nj * 2 + 1][1] = r3;
            }
#pragma unroll
            for (int mi = 0; mi < 2; mi++)
#pragma unroll
                for (int ni = 0; ni < 4; ni++) {
                    asm volatile(
                        "mma.sync.aligned.m16n8k16.row.col.f32.bf16.bf16.f32 "
                        "{%0,%1,%2,%3}, {%4,%5,%6,%7}, {%8,%9}, {%0,%1,%2,%3};"
                        : "+f"(acc[mi][ni][0]), "+f"(acc[mi][ni][1]),
                          "+f"(acc[mi][ni][2]), "+f"(acc[mi][ni][3])
                        : "r"(af[mi][0]), "r"(af[mi][1]), "r"(af[mi][2]), "r"(af[mi][3]),
                          "r"(bfr[ni][0]), "r"(bfr[ni][1]));
                }
        }

        if (st == NSTG - 1) {
            // c0,c1 = K row; c2,c3 = V row of SAME channel, same columns.
#pragma unroll
            for (int mi = 0; mi < 2; mi++)
#pragma unroll
                for (int ni = 0; ni < 4; ni++) {
                    float k0 = acc[mi][ni][0], k1 = acc[mi][ni][1];
                    float v0 = acc[mi][ni][2], v1 = acc[mi][ni][3];
                    skv[mi] += k0 * v0 + k1 * v1;
                    skk[mi] += k0 * k0 + k1 * k1;
                    svv[mi] += v0 * v0 + v1 * v1;
                }
        }
    }
#undef LOAD_B

    // quad reduce (lanes 4q..4q+3 share a channel row)
#pragma unroll
    for (int mi = 0; mi < 2; mi++) {
        skv[mi] += __shfl_down_sync(0xffffffffu, skv[mi], 1);
        skv[mi] += __shfl_down_sync(0xffffffffu, skv[mi], 2);
        skk[mi] += __shfl_down_sync(0xffffffffu, skk[mi], 1);
        skk[mi] += __shfl_down_sync(0xffffffffu, skk[mi], 2);
        svv[mi] += __shfl_down_sync(0xffffffffu, svv[mi], 1);
        svv[mi] += __shfl_down_sync(0xffffffffu, svv[mi], 2);
    }
    __syncthreads();   // sS zero-init visible (done at kernel start)
    if ((lane & 3) == 0) {
#pragma unroll
        for (int mi = 0; mi < 2; mi++) {
            int chl = (wm * 2 + mi) * 8 + (lane >> 2);
            atomicAdd(&sS[chl * 3 + 0], skv[mi]);
            atomicAdd(&sS[chl * 3 + 1], skk[mi]);
            atomicAdd(&sS[chl * 3 + 2], svv[mi]);
        }
    }
    __syncthreads();

    if (tid < 64) {
        float kv  = sS[tid * 3 + 0];
        float kk2 = sS[tid * 3 + 1];
        float vv2 = sS[tid * 3 + 2];
        float cosv = kv / ((sqrtf(kk2) + 1e-12f) * (sqrtf(vv2) + 1e-12f));
        g_A[b * C_ + cb * 64 + tid] = 0.5f * cosv + 0.5f;
    }
}

// ---------------------------------------------------------------------------
// Kernel 3: out = A[b,c] * X
// ---------------------------------------------------------------------------
__global__ void scale_kernel(const float* __restrict__ X, float* __restrict__ out) {
    int i = blockIdx.x * blockDim.x + threadIdx.x;
    const int n4 = B_ * C_ * HW_ / 4;
    if (i < n4) {
        float4 x = ((const float4*)X)[i];
        float a = g_A[i >> 8];
        float4 o;
        o.x = a * x.x; o.y = a * x.y; o.z = a * x.z; o.w = a * x.w;
        ((float4*)out)[i] = o;
    }
}

// ---------------------------------------------------------------------------
extern "C" void kernel_launch(void* const* d_in, const int* in_sizes, int n_in,
                              void* d_out, int out_size) {
    const float* X = (const float*)d_in[0];
    const float* W = (const float*)d_in[1];
    float* out = (float*)d_out;

    cudaFuncSetAttribute(attn_gemm_kernel,
                         cudaFuncAttributeMaxDynamicSharedMemorySize, SMEM_TOTAL);

    wprep_kernel<<<(2 * C_ * C_ / 4 + 255) / 256, 256>>>(W);
    norm_kernel<<<dim3(HW_ / 64, B_), 256>>>(X);
    attn_gemm_kernel<<<dim3(C_ / 64, B_), 256, SMEM_TOTAL>>>();

    const int n4 = B_ * C_ * HW_ / 4;
    scale_kernel<<<(n4 + 255) / 256, 256>>>(X, out);
}